// round 13
// baseline (speedup 1.0000x reference)
#include <cuda_runtime.h>
#include <cuda_fp16.h>
#include <math.h>
#include <stdint.h>

#define D    256
#define DL   256
#define S    2048
#define B    8
#define F    8192
#define NE   (B * F)
#define MAXIT (2 * NE)
#define TAB_PRED 2048
#define TAB_ROLE 3072
#define TAB_ROWS 3138
#define STAGE_PITCH 132
#define XMAT 8192                           // 128 rows x 64B
#define WMAT 16384                          // 256 rows x 64B
#define STAGE_BYTES (XMAT + WMAT)           // 24576
#define NSTAGE 4
#define DYN_SMEM (NSTAGE * STAGE_BYTES + 1024)   // 99328; epilogue 67584 fits
#define SWZ(o) ((o) ^ (((o) >> 3) & 0x70))

// ---------------- device scratch ----------------
__device__ float g_agg[B * S * D];
__device__ float g_pooled[B * D];
__device__ int   g_items[MAXIT];
__device__ int   g_count;
__device__ __align__(16) __half g_tab[TAB_ROWS * 256];
__device__ __align__(16) __half g_w1t[512 * 768];   // W1^T [n][k]
__device__ __align__(16) __half g_w2t[256 * 512];   // W2^T [n][k]
__device__ __align__(16) __half g_H[(size_t)MAXIT * 512];

__device__ __forceinline__ uint32_t smem_u32_of(const void* p) {
    uint32_t a;
    asm("{ .reg .u64 t; cvta.to.shared.u64 t, %1; cvt.u32.u64 %0, t; }" : "=r"(a) : "l"(p));
    return a;
}
__device__ __forceinline__ float gelu_e(float x) { return x * normcdff(x); }

#define LDSM4(r0, r1, r2, r3, addr) \
    asm volatile("ldmatrix.sync.aligned.m8n8.x4.shared.b16 {%0,%1,%2,%3}, [%4];" \
        : "=r"(r0), "=r"(r1), "=r"(r2), "=r"(r3) : "r"(addr))

#define MMA16816(c, a, b0, b1) \
    asm volatile("mma.sync.aligned.m16n8k16.row.col.f32.f16.f16.f32 " \
        "{%0,%1,%2,%3}, {%4,%5,%6,%7}, {%8,%9}, {%0,%1,%2,%3};" \
        : "+f"((c)[0]), "+f"((c)[1]), "+f"((c)[2]), "+f"((c)[3]) \
        : "r"((a)[0]), "r"((a)[1]), "r"((a)[2]), "r"((a)[3]), "r"(b0), "r"(b1))

#define CP16(dst, src) \
    asm volatile("cp.async.cg.shared.global [%0], [%1], 16;" \
        :: "r"(dst), "l"(__cvta_generic_to_global(src)) : "memory")
#define CP_COMMIT() asm volatile("cp.async.commit_group;" ::: "memory")
#define CP_WAIT2()  asm volatile("cp.async.wait_group 2;" ::: "memory")

// ---------------- zero ----------------
__global__ void zero_kernel() {
    int i = blockIdx.x * blockDim.x + threadIdx.x;
    if (i < B * S * D) g_agg[i] = 0.0f;
    if (i < B * D)     g_pooled[i] = 0.0f;
    if (i == 0)        g_count = 0;
}

// ---------------- compact ----------------
__global__ void compact_kernel(const int* __restrict__ mask, const int* __restrict__ is_role,
                               const int* __restrict__ add_rev) {
    int e = blockIdx.x * blockDim.x + threadIdx.x;
    if (e >= NE) return;
    if (!mask[e]) return;
    bool rev = (!is_role[e]) && add_rev[e];
    int slot = atomicAdd(&g_count, rev ? 2 : 1);
    g_items[slot] = e << 1;
    if (rev) g_items[slot + 1] = (e << 1) | 1;
}

// ---------------- prep: fp16 table + fp16 W^T ----------------
__global__ void prep_kernel(const float* __restrict__ pos, const float* __restrict__ pred,
                            const float* __restrict__ role,
                            const float* __restrict__ w1, const float* __restrict__ w2) {
    int tid = blockIdx.x * blockDim.x + threadIdx.x;
    const int NTAB = TAB_ROWS * 256;
    const int NW1 = 512 * 768;
    const int NW2 = 256 * 512;
    if (tid < NTAB) {
        int row = tid >> 8, col = tid & 255;
        float v;
        if (row < TAB_PRED)      v = pos[tid];
        else if (row < TAB_ROLE) v = pred[(row - TAB_PRED) * 256 + col];
        else                     v = role[(row - TAB_ROLE) * 256 + col];
        g_tab[tid] = __float2half(v);
    } else if (tid < NTAB + NW1) {
        int u = tid - NTAB;                    // u = n*768 + k
        int n = u / 768, k = u - n * 768;
        g_w1t[u] = __float2half(w1[(size_t)k * 512 + n]);
    } else if (tid < NTAB + NW1 + NW2) {
        int u = tid - NTAB - NW1;              // u = n*512 + k
        int n = u / 512, k = u - n * 512;
        g_w2t[u] = __float2half(w2[(size_t)k * 256 + n]);
    }
}

// ---------------- GEMM1: X[128x768] @ W1[768x512] -> gelu -> g_H ----------------
// grid = tiles x 2 n-halves; 256 thr; warp tile 32(M) x 128(N); CTA tile 128 x 256
__global__ void __launch_bounds__(256, 1)
gemm1_kernel(const int* __restrict__ pred_idx,
             const int* __restrict__ a0, const int* __restrict__ a1,
             const int* __restrict__ role_idx, const int* __restrict__ is_role,
             const float* __restrict__ b1) {
    extern __shared__ char smraw[];
    __shared__ int ssrc[128][3];

    int t = threadIdx.x;
    int tile = blockIdx.x >> 1, nq = blockIdx.x & 1;
    int count = g_count;
    int base = tile * 128;
    if (base >= count) return;
    int nE = min(128, count - base);

    if (t < 128) {
        int r0 = 0, r1 = TAB_PRED, r2 = 0;
        if (t < nE) {
            int item = g_items[base + t];
            int e = item >> 1, dir = item & 1;
            int i0 = a0[e], i1 = a1[e];
            r1 = TAB_PRED + pred_idx[e];
            if (dir == 0) {
                int rr = is_role[e];
                r0 = i0;
                r2 = rr ? (TAB_ROLE + role_idx[e]) : i1;
            } else { r0 = i1; r2 = i0; }
        }
        ssrc[t][0] = r0; ssrc[t][1] = r1; ssrc[t][2] = r2;
    }

    uint32_t raw = smem_u32_of(smraw);
    uint32_t smu = (raw + 1023u) & ~1023u;
    __syncthreads();

    int w = t >> 5, lane = t & 31;
    int wm = w >> 1, wn = w & 1;       // wm 0..3 (M 32-rows), wn 0..1 (N 128-half)
    int blk = lane >> 3, brow = lane & 7;

    float acc[128];
    #pragma unroll
    for (int i = 0; i < 128; i++) acc[i] = 0.0f;

    const int KC = 24;  // 768 / 32

    // fill: X chunk 512 cp, W chunk (256 n-rows) 1024 cp
    #define G1_FILL(kc_, st_) do { \
        uint32_t sb = smu + (st_) * STAGE_BYTES; \
        int seg_ = (kc_) >> 3; \
        int innb_ = ((kc_) & 7) * 64; \
        _Pragma("unroll") \
        for (int i = t; i < 512; i += 256) { \
            int e_ = i >> 2, q_ = i & 3; \
            const char* src_ = (const char*)g_tab \
                               + (size_t)ssrc[e_][seg_] * 512 + innb_ + q_ * 16; \
            CP16(sb + SWZ(e_ * 64 + q_ * 16), src_); \
        } \
        _Pragma("unroll") \
        for (int i = t; i < 1024; i += 256) { \
            int r_ = i >> 2, q_ = i & 3; \
            const char* src_ = (const char*)g_w1t \
                               + (size_t)(nq * 256 + r_) * 1536 + (kc_) * 64 + q_ * 16; \
            CP16(sb + XMAT + SWZ(r_ * 64 + q_ * 16), src_); \
        } \
    } while (0)

    G1_FILL(0, 0); CP_COMMIT();
    G1_FILL(1, 1); CP_COMMIT();
    G1_FILL(2, 2); CP_COMMIT();

    int st = 0;                 // stage of current chunk
    int stn = 3;                // stage to fill next (kc+3)
    for (int kc = 0; kc < KC; kc++) {
        CP_WAIT2();
        __syncthreads();        // all warps done with MMA(kc-1) => stage stn safe
        if (kc + 3 < KC) G1_FILL(kc + 3, stn);
        CP_COMMIT();

        uint32_t sb = smu + st * STAGE_BYTES;
        uint32_t x_u = sb;
        uint32_t w_u = sb + XMAT;

        #pragma unroll
        for (int kk = 0; kk < 2; kk++) {
            uint32_t ah[2][4];
            #pragma unroll
            for (int mf = 0; mf < 2; mf++) {
                uint32_t off = SWZ((uint32_t)(wm * 32 + mf * 16 + (blk & 1) * 8 + brow) * 64
                                   + kk * 32 + (blk >> 1) * 16);
                LDSM4(ah[mf][0], ah[mf][1], ah[mf][2], ah[mf][3], x_u + off);
            }
            #pragma unroll
            for (int nf2 = 0; nf2 < 8; nf2++) {
                uint32_t boff = SWZ((uint32_t)(wn * 128 + nf2 * 16 + (blk >> 1) * 8 + brow) * 64
                                    + kk * 32 + (blk & 1) * 16);
                uint32_t bh[4];
                LDSM4(bh[0], bh[1], bh[2], bh[3], w_u + boff);
                float* c0 = &acc[(nf2 * 2) * 4];
                float* c1 = &acc[(nf2 * 2 + 1) * 4];
                float* c2 = &acc[(16 + nf2 * 2) * 4];
                float* c3 = &acc[(16 + nf2 * 2 + 1) * 4];
                MMA16816(c0, ah[0], bh[0], bh[1]);
                MMA16816(c1, ah[0], bh[2], bh[3]);
                MMA16816(c2, ah[1], bh[0], bh[1]);
                MMA16816(c3, ah[1], bh[2], bh[3]);
            }
        }
        st = (st + 1 == NSTAGE) ? 0 : st + 1;
        stn = (stn + 1 == NSTAGE) ? 0 : stn + 1;
    }

    // ---- epilogue: two 128-col passes through smem stage ----
    float* stage = (float*)smraw;
    int g = lane >> 2, i2 = (lane & 3) * 2;
    #pragma unroll
    for (int ph = 0; ph < 2; ph++) {
        __syncthreads();
        if (wn == ph) {
            #pragma unroll
            for (int mf = 0; mf < 2; mf++)
                #pragma unroll
                for (int nf = 0; nf < 16; nf++) {
                    float* c = &acc[(mf * 16 + nf) * 4];
                    int r = wm * 32 + mf * 16 + g;
                    int col = nf * 8 + i2;
                    stage[r * STAGE_PITCH + col]     = c[0];
                    stage[r * STAGE_PITCH + col + 1] = c[1];
                    stage[(r + 8) * STAGE_PITCH + col]     = c[2];
                    stage[(r + 8) * STAGE_PITCH + col + 1] = c[3];
                }
        }
        __syncthreads();
        int col = t & 127, eh = t >> 7;
        int gcol = nq * 256 + ph * 128 + col;
        float bias = b1[gcol];
        for (int e = eh; e < nE; e += 2) {
            float x = stage[e * STAGE_PITCH + col] + bias;
            g_H[(size_t)(base + e) * 512 + gcol] = __float2half(gelu_e(x));
        }
    }
}

// ---------------- GEMM2: H[128x512] @ W2[512x256] -> +b2 -> atomic scatter ----------------
// grid = tiles; CTA tile 128 x 256 (full N); warp tile 32x128
__global__ void __launch_bounds__(256, 1)
gemm2_kernel(const int* __restrict__ a0, const int* __restrict__ a1,
             const int* __restrict__ is_role, const float* __restrict__ b2) {
    extern __shared__ char smraw[];
    __shared__ int stgt[128];

    int t = threadIdx.x;
    int tile = blockIdx.x;
    int count = g_count;
    int base = tile * 128;
    if (base >= count) return;
    int nE = min(128, count - base);

    if (t < 128) {
        int tg = 0, bidx = 0;
        if (t < nE) {
            int item = g_items[base + t];
            int e = item >> 1, dir = item & 1;
            bidx = e >> 13;
            int i0 = a0[e], i1 = a1[e];
            if (dir == 0) { int rr = is_role[e]; tg = rr ? i0 : i1; }
            else tg = i0;
        }
        stgt[t] = (bidx * S + tg) * D;
    }

    uint32_t raw = smem_u32_of(smraw);
    uint32_t smu = (raw + 1023u) & ~1023u;
    __syncthreads();

    int w = t >> 5, lane = t & 31;
    int wm = w >> 1, wn = w & 1;
    int blk = lane >> 3, brow = lane & 7;

    float acc[128];
    #pragma unroll
    for (int i = 0; i < 128; i++) acc[i] = 0.0f;

    const int KC = 16;  // 512 / 32

    #define G2_FILL(kc_, st_) do { \
        uint32_t sb = smu + (st_) * STAGE_BYTES; \
        _Pragma("unroll") \
        for (int i = t; i < 512; i += 256) { \
            int e_ = i >> 2, q_ = i & 3; \
            const char* src_ = (const char*)g_H \
                               + (size_t)(base + e_) * 1024 + (kc_) * 64 + q_ * 16; \
            CP16(sb + SWZ(e_ * 64 + q_ * 16), src_); \
        } \
        _Pragma("unroll") \
        for (int i = t; i < 1024; i += 256) { \
            int r_ = i >> 2, q_ = i & 3; \
            const char* src_ = (const char*)g_w2t \
                               + (size_t)r_ * 1024 + (kc_) * 64 + q_ * 16; \
            CP16(sb + XMAT + SWZ(r_ * 64 + q_ * 16), src_); \
        } \
    } while (0)

    G2_FILL(0, 0); CP_COMMIT();
    G2_FILL(1, 1); CP_COMMIT();
    G2_FILL(2, 2); CP_COMMIT();

    int st = 0, stn = 3;
    for (int kc = 0; kc < KC; kc++) {
        CP_WAIT2();
        __syncthreads();
        if (kc + 3 < KC) G2_FILL(kc + 3, stn);
        CP_COMMIT();

        uint32_t sb = smu + st * STAGE_BYTES;
        uint32_t x_u = sb;
        uint32_t w_u = sb + XMAT;

        #pragma unroll
        for (int kk = 0; kk < 2; kk++) {
            uint32_t ah[2][4];
            #pragma unroll
            for (int mf = 0; mf < 2; mf++) {
                uint32_t off = SWZ((uint32_t)(wm * 32 + mf * 16 + (blk & 1) * 8 + brow) * 64
                                   + kk * 32 + (blk >> 1) * 16);
                LDSM4(ah[mf][0], ah[mf][1], ah[mf][2], ah[mf][3], x_u + off);
            }
            #pragma unroll
            for (int nf2 = 0; nf2 < 8; nf2++) {
                uint32_t boff = SWZ((uint32_t)(wn * 128 + nf2 * 16 + (blk >> 1) * 8 + brow) * 64
                                    + kk * 32 + (blk & 1) * 16);
                uint32_t bh[4];
                LDSM4(bh[0], bh[1], bh[2], bh[3], w_u + boff);
                float* c0 = &acc[(nf2 * 2) * 4];
                float* c1 = &acc[(nf2 * 2 + 1) * 4];
                float* c2 = &acc[(16 + nf2 * 2) * 4];
                float* c3 = &acc[(16 + nf2 * 2 + 1) * 4];
                MMA16816(c0, ah[0], bh[0], bh[1]);
                MMA16816(c1, ah[0], bh[2], bh[3]);
                MMA16816(c2, ah[1], bh[0], bh[1]);
                MMA16816(c3, ah[1], bh[2], bh[3]);
            }
        }
        st = (st + 1 == NSTAGE) ? 0 : st + 1;
        stn = (stn + 1 == NSTAGE) ? 0 : stn + 1;
    }

    // ---- epilogue: two 128-col passes, atomic scatter ----
    float* stage = (float*)smraw;
    int g = lane >> 2, i2 = (lane & 3) * 2;
    #pragma unroll
    for (int ph = 0; ph < 2; ph++) {
        __syncthreads();
        if (wn == ph) {
            #pragma unroll
            for (int mf = 0; mf < 2; mf++)
                #pragma unroll
                for (int nf = 0; nf < 16; nf++) {
                    float* c = &acc[(mf * 16 + nf) * 4];
                    int r = wm * 32 + mf * 16 + g;
                    int col = nf * 8 + i2;
                    stage[r * STAGE_PITCH + col]     = c[0];
                    stage[r * STAGE_PITCH + col + 1] = c[1];
                    stage[(r + 8) * STAGE_PITCH + col]     = c[2];
                    stage[(r + 8) * STAGE_PITCH + col + 1] = c[3];
                }
        }
        __syncthreads();
        int col = t & 127, eh = t >> 7;
        int gcol = ph * 128 + col;
        float bias = b2[gcol];
        for (int e = eh; e < nE; e += 2)
            atomicAdd(&g_agg[stgt[e] + gcol], stage[e * STAGE_PITCH + col] + bias);
    }
}

// ---------------- layernorm + pooled mean ----------------
__global__ void norm_pool_kernel(const float* __restrict__ pos,
                                 const float* __restrict__ ln_g,
                                 const float* __restrict__ ln_b) {
    int b = blockIdx.y;
    int s_base = blockIdx.x * 32;
    int warp = threadIdx.x >> 5, lane = threadIdx.x & 31;
    float gg[8], be[8], pacc[8];
    #pragma unroll
    for (int i = 0; i < 8; i++) {
        gg[i] = ln_g[i * 32 + lane]; be[i] = ln_b[i * 32 + lane]; pacc[i] = 0.0f;
    }
    for (int r = warp; r < 32; r += 8) {
        int ss = s_base + r;
        const float* ag = &g_agg[((size_t)b * S + ss) * D];
        const float* ps = &pos[(size_t)ss * D];
        float x[8]; float sum = 0.0f;
        #pragma unroll
        for (int i = 0; i < 8; i++) { x[i] = ps[i * 32 + lane] + ag[i * 32 + lane]; sum += x[i]; }
        #pragma unroll
        for (int off = 16; off > 0; off >>= 1) sum += __shfl_xor_sync(0xFFFFFFFFu, sum, off);
        float mu = sum * (1.0f / D); float v = 0.0f;
        #pragma unroll
        for (int i = 0; i < 8; i++) { x[i] -= mu; v += x[i] * x[i]; }
        #pragma unroll
        for (int off = 16; off > 0; off >>= 1) v += __shfl_xor_sync(0xFFFFFFFFu, v, off);
        float inv = rsqrtf(v * (1.0f / D) + 1e-5f);
        #pragma unroll
        for (int i = 0; i < 8; i++) pacc[i] += x[i] * inv * gg[i] + be[i];
    }
    __shared__ float sp[256];
    sp[threadIdx.x] = 0.0f;
    __syncthreads();
    #pragma unroll
    for (int i = 0; i < 8; i++) atomicAdd(&sp[i * 32 + lane], pacc[i]);
    __syncthreads();
    atomicAdd(&g_pooled[b * D + threadIdx.x], sp[threadIdx.x] * (1.0f / S));
}

// ---------------- final small MLP ----------------
__global__ void final_kernel(const float* __restrict__ lw1, const float* __restrict__ lb1,
                             const float* __restrict__ lw2, const float* __restrict__ lb2,
                             float* __restrict__ out) {
    __shared__ float P[B * D];
    __shared__ float Hh[B * DL];
    int t = threadIdx.x;
    for (int i = t; i < B * D; i += 256) P[i] = g_pooled[i];
    __syncthreads();
    float a[B];
    #pragma unroll
    for (int b = 0; b < B; b++) a[b] = lb1[t];
    for (int k = 0; k < D; k++) {
        float wv = lw1[k * DL + t];
        #pragma unroll
        for (int b = 0; b < B; b++) a[b] = fmaf(P[b * D + k], wv, a[b]);
    }
    #pragma unroll
    for (int b = 0; b < B; b++) Hh[b * DL + t] = gelu_e(a[b]);
    __syncthreads();
    #pragma unroll
    for (int b = 0; b < B; b++) a[b] = lb2[t];
    for (int k = 0; k < DL; k++) {
        float wv = lw2[k * DL + t];
        #pragma unroll
        for (int b = 0; b < B; b++) a[b] = fmaf(Hh[b * DL + k], wv, a[b]);
    }
    #pragma unroll
    for (int b = 0; b < B; b++) out[b * DL + t] = a[b];
}

// ---------------- launch ----------------
extern "C" void kernel_launch(void* const* d_in, const int* in_sizes, int n_in,
                              void* d_out, int out_size) {
    const float* pos_emb  = (const float*)d_in[0];
    const float* pred_emb = (const float*)d_in[1];
    const float* role_emb = (const float*)d_in[2];
    const float* w1       = (const float*)d_in[3];
    const float* b1       = (const float*)d_in[4];
    const float* w2       = (const float*)d_in[5];
    const float* b2       = (const float*)d_in[6];
    const float* ln_g     = (const float*)d_in[7];
    const float* ln_b     = (const float*)d_in[8];
    const float* lw1      = (const float*)d_in[9];
    const float* lb1      = (const float*)d_in[10];
    const float* lw2      = (const float*)d_in[11];
    const float* lb2      = (const float*)d_in[12];
    const int* pred_idx   = (const int*)d_in[13];
    const int* a0         = (const int*)d_in[14];
    const int* a1         = (const int*)d_in[15];
    const int* role_idx   = (const int*)d_in[16];
    const int* is_role    = (const int*)d_in[17];
    const int* add_rev    = (const int*)d_in[18];
    const int* mask       = (const int*)d_in[19];
    float* out = (float*)d_out;

    cudaFuncSetAttribute(gemm1_kernel, cudaFuncAttributeMaxDynamicSharedMemorySize, DYN_SMEM);
    cudaFuncSetAttribute(gemm2_kernel, cudaFuncAttributeMaxDynamicSharedMemorySize, DYN_SMEM);

    zero_kernel<<<(B * S * D + 255) / 256, 256>>>();
    compact_kernel<<<(NE + 255) / 256, 256>>>(mask, is_role, add_rev);
    {
        int total = TAB_ROWS * 256 + 512 * 768 + 256 * 512;
        prep_kernel<<<(total + 255) / 256, 256>>>(pos_emb, pred_emb, role_emb, w1, w2);
    }
    gemm1_kernel<<<(MAXIT / 128) * 2, 256, DYN_SMEM>>>(pred_idx, a0, a1, role_idx, is_role, b1);
    gemm2_kernel<<<MAXIT / 128, 256, DYN_SMEM>>>(a0, a1, is_role, b2);
    dim3 g(S / 32, B);
    norm_pool_kernel<<<g, 256>>>(pos_emb, ln_g, ln_b);
    final_kernel<<<1, 256>>>(lw1, lb1, lw2, lb2, out);
}

// round 14
// speedup vs baseline: 1.2894x; 1.2894x over previous
#include <cuda_runtime.h>
#include <cuda_fp16.h>
#include <math.h>
#include <stdint.h>

#define D    256
#define DL   256
#define S    2048
#define B    8
#define F    8192
#define NE   (B * F)
#define MAXIT (2 * NE)
#define TAB_PRED 2048
#define TAB_ROLE 3072
#define TAB_ROWS 3138
#define MAT_BYTES 8192                      // 128 rows x 64B (k=32 fp16), packed + swizzled
#define STAGE_BYTES (2 * MAT_BYTES)         // X + W = 16384
#define NSTAGE 5
#define DYN_SMEM (NSTAGE * STAGE_BYTES + 1024)   // 82944
#define SWZ(o) ((o) ^ (((o) >> 3) & 0x70))

// ---------------- device scratch ----------------
__device__ float g_agg[B * S * D];
__device__ float g_pooled[B * D];
__device__ int   g_items[MAXIT];
__device__ int   g_count;
__device__ __align__(16) __half g_tab[TAB_ROWS * 256];
__device__ __align__(16) __half g_w1t[512 * 768];   // W1^T [n][k]
__device__ __align__(16) __half g_w2t[256 * 512];   // W2^T [n][k]
__device__ __align__(16) __half g_H[(size_t)MAXIT * 512];

__device__ __forceinline__ uint32_t smem_u32_of(const void* p) {
    uint32_t a;
    asm("{ .reg .u64 t; cvta.to.shared.u64 t, %1; cvt.u32.u64 %0, t; }" : "=r"(a) : "l"(p));
    return a;
}
__device__ __forceinline__ float gelu_e(float x) { return x * normcdff(x); }
// fast gelu: even series of x*Phi(x), |err|<5e-6 for |x|<0.5; exact fallback beyond
__device__ __forceinline__ float gelu_f(float x) {
    float x2 = x * x;
    if (fabsf(x) < 0.5f) {
        return fmaf(x2, fmaf(x2, fmaf(x2, 0.00997356f, -0.06649038f), 0.39894228f), 0.5f * x);
    }
    return x * normcdff(x);
}

#define LDSM4(r0, r1, r2, r3, addr) \
    asm volatile("ldmatrix.sync.aligned.m8n8.x4.shared.b16 {%0,%1,%2,%3}, [%4];" \
        : "=r"(r0), "=r"(r1), "=r"(r2), "=r"(r3) : "r"(addr))

#define MMA16816(c, a, b0, b1) \
    asm volatile("mma.sync.aligned.m16n8k16.row.col.f32.f16.f16.f32 " \
        "{%0,%1,%2,%3}, {%4,%5,%6,%7}, {%8,%9}, {%0,%1,%2,%3};" \
        : "+f"((c)[0]), "+f"((c)[1]), "+f"((c)[2]), "+f"((c)[3]) \
        : "r"((a)[0]), "r"((a)[1]), "r"((a)[2]), "r"((a)[3]), "r"(b0), "r"(b1))

#define CP16(dst, src) \
    asm volatile("cp.async.cg.shared.global [%0], [%1], 16;" \
        :: "r"(dst), "l"(__cvta_generic_to_global(src)) : "memory")
#define CP_COMMIT() asm volatile("cp.async.commit_group;" ::: "memory")
#define CP_WAIT3()  asm volatile("cp.async.wait_group 3;" ::: "memory")

// ---------------- zero ----------------
__global__ void zero_kernel() {
    int i = blockIdx.x * blockDim.x + threadIdx.x;
    if (i < B * S * D) g_agg[i] = 0.0f;
    if (i < B * D)     g_pooled[i] = 0.0f;
    if (i == 0)        g_count = 0;
}

// ---------------- compact ----------------
__global__ void compact_kernel(const int* __restrict__ mask, const int* __restrict__ is_role,
                               const int* __restrict__ add_rev) {
    int e = blockIdx.x * blockDim.x + threadIdx.x;
    if (e >= NE) return;
    if (!mask[e]) return;
    bool rev = (!is_role[e]) && add_rev[e];
    int slot = atomicAdd(&g_count, rev ? 2 : 1);
    g_items[slot] = e << 1;
    if (rev) g_items[slot + 1] = (e << 1) | 1;
}

// ---------------- prep: fp16 table + fp16 W^T ----------------
__global__ void prep_kernel(const float* __restrict__ pos, const float* __restrict__ pred,
                            const float* __restrict__ role,
                            const float* __restrict__ w1, const float* __restrict__ w2) {
    int tid = blockIdx.x * blockDim.x + threadIdx.x;
    const int NTAB = TAB_ROWS * 256;
    const int NW1 = 512 * 768;
    const int NW2 = 256 * 512;
    if (tid < NTAB) {
        int row = tid >> 8, col = tid & 255;
        float v;
        if (row < TAB_PRED)      v = pos[tid];
        else if (row < TAB_ROLE) v = pred[(row - TAB_PRED) * 256 + col];
        else                     v = role[(row - TAB_ROLE) * 256 + col];
        g_tab[tid] = __float2half(v);
    } else if (tid < NTAB + NW1) {
        int u = tid - NTAB;                    // u = n*768 + k
        int n = u / 768, k = u - n * 768;
        g_w1t[u] = __float2half(w1[(size_t)k * 512 + n]);
    } else if (tid < NTAB + NW1 + NW2) {
        int u = tid - NTAB - NW1;              // u = n*512 + k
        int n = u / 512, k = u - n * 512;
        g_w2t[u] = __float2half(w2[(size_t)k * 256 + n]);
    }
}

// ---------------- GEMM1: X[128x768] @ W1[768x512] -> gelu -> g_H ----------------
// grid = tiles x 4 n-quarters; 5-stage cp.async; warp tile 32x64; fragment-direct epilogue
__global__ void __launch_bounds__(256, 2)
gemm1_kernel(const int* __restrict__ pred_idx,
             const int* __restrict__ a0, const int* __restrict__ a1,
             const int* __restrict__ role_idx, const int* __restrict__ is_role,
             const float* __restrict__ b1) {
    extern __shared__ char smraw[];
    __shared__ int ssrc[128][3];
    __shared__ float sb1[128];

    int t = threadIdx.x;
    int tile = blockIdx.x >> 2, nq = blockIdx.x & 3;
    int count = g_count;
    int base = tile * 128;
    if (base >= count) return;
    int nE = min(128, count - base);

    if (t < 128) {
        int r0 = 0, r1 = TAB_PRED, r2 = 0;
        if (t < nE) {
            int item = g_items[base + t];
            int e = item >> 1, dir = item & 1;
            int i0 = a0[e], i1 = a1[e];
            r1 = TAB_PRED + pred_idx[e];
            if (dir == 0) {
                int rr = is_role[e];
                r0 = i0;
                r2 = rr ? (TAB_ROLE + role_idx[e]) : i1;
            } else { r0 = i1; r2 = i0; }
        }
        ssrc[t][0] = r0; ssrc[t][1] = r1; ssrc[t][2] = r2;
        sb1[t] = b1[nq * 128 + t];
    }

    uint32_t raw = smem_u32_of(smraw);
    uint32_t smu = (raw + 1023u) & ~1023u;
    __syncthreads();

    int w = t >> 5, lane = t & 31;
    int wm = w >> 1, wn = w & 1;
    int blk = lane >> 3, brow = lane & 7;

    float acc[64];
    #pragma unroll
    for (int i = 0; i < 64; i++) acc[i] = 0.0f;

    const int KC = 24;  // 768 / 32

    #define G1_FILL(kc_, st_) do { \
        uint32_t sb = smu + (st_) * STAGE_BYTES; \
        int seg_ = (kc_) >> 3; \
        int innb_ = ((kc_) & 7) * 64; \
        _Pragma("unroll") \
        for (int i = t; i < 512; i += 256) { \
            int e_ = i >> 2, q_ = i & 3; \
            const char* src_ = (const char*)g_tab \
                               + (size_t)ssrc[e_][seg_] * 512 + innb_ + q_ * 16; \
            CP16(sb + SWZ(e_ * 64 + q_ * 16), src_); \
        } \
        _Pragma("unroll") \
        for (int i = t; i < 512; i += 256) { \
            int r_ = i >> 2, q_ = i & 3; \
            const char* src_ = (const char*)g_w1t \
                               + (size_t)(nq * 128 + r_) * 1536 + (kc_) * 64 + q_ * 16; \
            CP16(sb + MAT_BYTES + SWZ(r_ * 64 + q_ * 16), src_); \
        } \
    } while (0)

    G1_FILL(0, 0); CP_COMMIT();
    G1_FILL(1, 1); CP_COMMIT();
    G1_FILL(2, 2); CP_COMMIT();
    G1_FILL(3, 3); CP_COMMIT();

    int st = 0;
    int stn = 4;
    for (int kc = 0; kc < KC; kc++) {
        CP_WAIT3();
        __syncthreads();
        if (kc + 4 < KC) G1_FILL(kc + 4, stn);
        CP_COMMIT();

        uint32_t sb = smu + st * STAGE_BYTES;
        uint32_t x_u = sb;
        uint32_t w_u = sb + MAT_BYTES;

        #pragma unroll
        for (int kk = 0; kk < 2; kk++) {
            uint32_t ah[2][4];
            #pragma unroll
            for (int mf = 0; mf < 2; mf++) {
                uint32_t off = SWZ((uint32_t)(wm * 32 + mf * 16 + (blk & 1) * 8 + brow) * 64
                                   + kk * 32 + (blk >> 1) * 16);
                LDSM4(ah[mf][0], ah[mf][1], ah[mf][2], ah[mf][3], x_u + off);
            }
            #pragma unroll
            for (int nf2 = 0; nf2 < 4; nf2++) {
                uint32_t boff = SWZ((uint32_t)(wn * 64 + nf2 * 16 + (blk >> 1) * 8 + brow) * 64
                                    + kk * 32 + (blk & 1) * 16);
                uint32_t bh[4];
                LDSM4(bh[0], bh[1], bh[2], bh[3], w_u + boff);
                float* c0 = &acc[(nf2 * 2) * 4];
                float* c1 = &acc[(nf2 * 2 + 1) * 4];
                float* c2 = &acc[(8 + nf2 * 2) * 4];
                float* c3 = &acc[(8 + nf2 * 2 + 1) * 4];
                MMA16816(c0, ah[0], bh[0], bh[1]);
                MMA16816(c1, ah[0], bh[2], bh[3]);
                MMA16816(c2, ah[1], bh[0], bh[1]);
                MMA16816(c3, ah[1], bh[2], bh[3]);
            }
        }
        st = (st + 1 == NSTAGE) ? 0 : st + 1;
        stn = (stn + 1 == NSTAGE) ? 0 : stn + 1;
    }

    // ---- fragment-direct epilogue: bias + fast gelu -> g_H (half2 stores) ----
    {
        int g = lane >> 2, i2 = (lane & 3) * 2;
        #pragma unroll
        for (int mh = 0; mh < 2; mh++) {
            #pragma unroll
            for (int nf2 = 0; nf2 < 4; nf2++) {
                #pragma unroll
                for (int p = 0; p < 2; p++) {
                    float* c = &acc[(mh * 8 + nf2 * 2 + p) * 4];
                    int lcol = wn * 64 + nf2 * 16 + p * 8 + i2;
                    int gcol = nq * 128 + lcol;
                    float2 bb = *(const float2*)&sb1[lcol];
                    int r0 = wm * 32 + mh * 16 + g;
                    __half2 h0 = __floats2half2_rn(gelu_f(c[0] + bb.x), gelu_f(c[1] + bb.y));
                    __half2 h1 = __floats2half2_rn(gelu_f(c[2] + bb.x), gelu_f(c[3] + bb.y));
                    *(__half2*)&g_H[(size_t)(base + r0) * 512 + gcol] = h0;
                    *(__half2*)&g_H[(size_t)(base + r0 + 8) * 512 + gcol] = h1;
                }
            }
        }
    }
}

// ---------------- GEMM2: H[128x512] @ W2[512x256] -> +b2 -> atomic scatter ----------------
// grid = tiles x 2 n-halves; warp tile 32x64; fragment-direct atomic epilogue
__global__ void __launch_bounds__(256, 2)
gemm2_kernel(const int* __restrict__ a0, const int* __restrict__ a1,
             const int* __restrict__ is_role, const float* __restrict__ b2) {
    extern __shared__ char smraw[];
    __shared__ int stgt[128];
    __shared__ float sb2[128];

    int t = threadIdx.x;
    int tile = blockIdx.x >> 1, nq = blockIdx.x & 1;
    int count = g_count;
    int base = tile * 128;
    if (base >= count) return;
    int nE = min(128, count - base);

    if (t < 128) {
        int tg = 0, bidx = 0;
        if (t < nE) {
            int item = g_items[base + t];
            int e = item >> 1, dir = item & 1;
            bidx = e >> 13;
            int i0 = a0[e], i1 = a1[e];
            if (dir == 0) { int rr = is_role[e]; tg = rr ? i0 : i1; }
            else tg = i0;
        }
        stgt[t] = (bidx * S + tg) * D;
        sb2[t] = b2[nq * 128 + t];
    }

    uint32_t raw = smem_u32_of(smraw);
    uint32_t smu = (raw + 1023u) & ~1023u;
    __syncthreads();

    int w = t >> 5, lane = t & 31;
    int wm = w >> 1, wn = w & 1;
    int blk = lane >> 3, brow = lane & 7;

    float acc[64];
    #pragma unroll
    for (int i = 0; i < 64; i++) acc[i] = 0.0f;

    const int KC = 16;  // 512 / 32

    #define G2_FILL(kc_, st_) do { \
        uint32_t sb = smu + (st_) * STAGE_BYTES; \
        _Pragma("unroll") \
        for (int i = t; i < 512; i += 256) { \
            int e_ = i >> 2, q_ = i & 3; \
            const char* src_ = (const char*)g_H \
                               + (size_t)(base + e_) * 1024 + (kc_) * 64 + q_ * 16; \
            CP16(sb + SWZ(e_ * 64 + q_ * 16), src_); \
        } \
        _Pragma("unroll") \
        for (int i = t; i < 512; i += 256) { \
            int r_ = i >> 2, q_ = i & 3; \
            const char* src_ = (const char*)g_w2t \
                               + (size_t)(nq * 128 + r_) * 1024 + (kc_) * 64 + q_ * 16; \
            CP16(sb + MAT_BYTES + SWZ(r_ * 64 + q_ * 16), src_); \
        } \
    } while (0)

    G2_FILL(0, 0); CP_COMMIT();
    G2_FILL(1, 1); CP_COMMIT();
    G2_FILL(2, 2); CP_COMMIT();
    G2_FILL(3, 3); CP_COMMIT();

    int st = 0, stn = 4;
    for (int kc = 0; kc < KC; kc++) {
        CP_WAIT3();
        __syncthreads();
        if (kc + 4 < KC) G2_FILL(kc + 4, stn);
        CP_COMMIT();

        uint32_t sb = smu + st * STAGE_BYTES;
        uint32_t x_u = sb;
        uint32_t w_u = sb + MAT_BYTES;

        #pragma unroll
        for (int kk = 0; kk < 2; kk++) {
            uint32_t ah[2][4];
            #pragma unroll
            for (int mf = 0; mf < 2; mf++) {
                uint32_t off = SWZ((uint32_t)(wm * 32 + mf * 16 + (blk & 1) * 8 + brow) * 64
                                   + kk * 32 + (blk >> 1) * 16);
                LDSM4(ah[mf][0], ah[mf][1], ah[mf][2], ah[mf][3], x_u + off);
            }
            #pragma unroll
            for (int nf2 = 0; nf2 < 4; nf2++) {
                uint32_t boff = SWZ((uint32_t)(wn * 64 + nf2 * 16 + (blk >> 1) * 8 + brow) * 64
                                    + kk * 32 + (blk & 1) * 16);
                uint32_t bh[4];
                LDSM4(bh[0], bh[1], bh[2], bh[3], w_u + boff);
                float* c0 = &acc[(nf2 * 2) * 4];
                float* c1 = &acc[(nf2 * 2 + 1) * 4];
                float* c2 = &acc[(8 + nf2 * 2) * 4];
                float* c3 = &acc[(8 + nf2 * 2 + 1) * 4];
                MMA16816(c0, ah[0], bh[0], bh[1]);
                MMA16816(c1, ah[0], bh[2], bh[3]);
                MMA16816(c2, ah[1], bh[0], bh[1]);
                MMA16816(c3, ah[1], bh[2], bh[3]);
            }
        }
        st = (st + 1 == NSTAGE) ? 0 : st + 1;
        stn = (stn + 1 == NSTAGE) ? 0 : stn + 1;
    }

    // ---- fragment-direct epilogue: +b2, guarded atomic scatter ----
    {
        int g = lane >> 2, i2 = (lane & 3) * 2;
        #pragma unroll
        for (int mh = 0; mh < 2; mh++) {
            #pragma unroll
            for (int nf2 = 0; nf2 < 4; nf2++) {
                #pragma unroll
                for (int p = 0; p < 2; p++) {
                    float* c = &acc[(mh * 8 + nf2 * 2 + p) * 4];
                    int lcol = wn * 64 + nf2 * 16 + p * 8 + i2;
                    int gcol = nq * 128 + lcol;
                    float2 bb = *(const float2*)&sb2[lcol];
                    int r0 = wm * 32 + mh * 16 + g;
                    if (r0 < nE) {
                        float* dst = &g_agg[stgt[r0] + gcol];
                        atomicAdd(dst,     c[0] + bb.x);
                        atomicAdd(dst + 1, c[1] + bb.y);
                    }
                    if (r0 + 8 < nE) {
                        float* dst = &g_agg[stgt[r0 + 8] + gcol];
                        atomicAdd(dst,     c[2] + bb.x);
                        atomicAdd(dst + 1, c[3] + bb.y);
                    }
                }
            }
        }
    }
}

// ---------------- layernorm + pooled mean ----------------
__global__ void norm_pool_kernel(const float* __restrict__ pos,
                                 const float* __restrict__ ln_g,
                                 const float* __restrict__ ln_b) {
    int b = blockIdx.y;
    int s_base = blockIdx.x * 32;
    int warp = threadIdx.x >> 5, lane = threadIdx.x & 31;
    float gg[8], be[8], pacc[8];
    #pragma unroll
    for (int i = 0; i < 8; i++) {
        gg[i] = ln_g[i * 32 + lane]; be[i] = ln_b[i * 32 + lane]; pacc[i] = 0.0f;
    }
    for (int r = warp; r < 32; r += 8) {
        int ss = s_base + r;
        const float* ag = &g_agg[((size_t)b * S + ss) * D];
        const float* ps = &pos[(size_t)ss * D];
        float x[8]; float sum = 0.0f;
        #pragma unroll
        for (int i = 0; i < 8; i++) { x[i] = ps[i * 32 + lane] + ag[i * 32 + lane]; sum += x[i]; }
        #pragma unroll
        for (int off = 16; off > 0; off >>= 1) sum += __shfl_xor_sync(0xFFFFFFFFu, sum, off);
        float mu = sum * (1.0f / D); float v = 0.0f;
        #pragma unroll
        for (int i = 0; i < 8; i++) { x[i] -= mu; v += x[i] * x[i]; }
        #pragma unroll
        for (int off = 16; off > 0; off >>= 1) v += __shfl_xor_sync(0xFFFFFFFFu, v, off);
        float inv = rsqrtf(v * (1.0f / D) + 1e-5f);
        #pragma unroll
        for (int i = 0; i < 8; i++) pacc[i] += x[i] * inv * gg[i] + be[i];
    }
    __shared__ float sp[256];
    sp[threadIdx.x] = 0.0f;
    __syncthreads();
    #pragma unroll
    for (int i = 0; i < 8; i++) atomicAdd(&sp[i * 32 + lane], pacc[i]);
    __syncthreads();
    atomicAdd(&g_pooled[b * D + threadIdx.x], sp[threadIdx.x] * (1.0f / S));
}

// ---------------- final small MLP ----------------
__global__ void final_kernel(const float* __restrict__ lw1, const float* __restrict__ lb1,
                             const float* __restrict__ lw2, const float* __restrict__ lb2,
                             float* __restrict__ out) {
    __shared__ float P[B * D];
    __shared__ float Hh[B * DL];
    int t = threadIdx.x;
    for (int i = t; i < B * D; i += 256) P[i] = g_pooled[i];
    __syncthreads();
    float a[B];
    #pragma unroll
    for (int b = 0; b < B; b++) a[b] = lb1[t];
    for (int k = 0; k < D; k++) {
        float wv = lw1[k * DL + t];
        #pragma unroll
        for (int b = 0; b < B; b++) a[b] = fmaf(P[b * D + k], wv, a[b]);
    }
    #pragma unroll
    for (int b = 0; b < B; b++) Hh[b * DL + t] = gelu_e(a[b]);
    __syncthreads();
    #pragma unroll
    for (int b = 0; b < B; b++) a[b] = lb2[t];
    for (int k = 0; k < DL; k++) {
        float wv = lw2[k * DL + t];
        #pragma unroll
        for (int b = 0; b < B; b++) a[b] = fmaf(Hh[b * DL + k], wv, a[b]);
    }
    #pragma unroll
    for (int b = 0; b < B; b++) out[b * DL + t] = a[b];
}

// ---------------- launch ----------------
extern "C" void kernel_launch(void* const* d_in, const int* in_sizes, int n_in,
                              void* d_out, int out_size) {
    const float* pos_emb  = (const float*)d_in[0];
    const float* pred_emb = (const float*)d_in[1];
    const float* role_emb = (const float*)d_in[2];
    const float* w1       = (const float*)d_in[3];
    const float* b1       = (const float*)d_in[4];
    const float* w2       = (const float*)d_in[5];
    const float* b2       = (const float*)d_in[6];
    const float* ln_g     = (const float*)d_in[7];
    const float* ln_b     = (const float*)d_in[8];
    const float* lw1      = (const float*)d_in[9];
    const float* lb1      = (const float*)d_in[10];
    const float* lw2      = (const float*)d_in[11];
    const float* lb2      = (const float*)d_in[12];
    const int* pred_idx   = (const int*)d_in[13];
    const int* a0         = (const int*)d_in[14];
    const int* a1         = (const int*)d_in[15];
    const int* role_idx   = (const int*)d_in[16];
    const int* is_role    = (const int*)d_in[17];
    const int* add_rev    = (const int*)d_in[18];
    const int* mask       = (const int*)d_in[19];
    float* out = (float*)d_out;

    cudaFuncSetAttribute(gemm1_kernel, cudaFuncAttributeMaxDynamicSharedMemorySize, DYN_SMEM);
    cudaFuncSetAttribute(gemm2_kernel, cudaFuncAttributeMaxDynamicSharedMemorySize, DYN_SMEM);

    zero_kernel<<<(B * S * D + 255) / 256, 256>>>();
    compact_kernel<<<(NE + 255) / 256, 256>>>(mask, is_role, add_rev);
    {
        int total = TAB_ROWS * 256 + 512 * 768 + 256 * 512;
        prep_kernel<<<(total + 255) / 256, 256>>>(pos_emb, pred_emb, role_emb, w1, w2);
    }
    gemm1_kernel<<<(MAXIT / 128) * 4, 256, DYN_SMEM>>>(pred_idx, a0, a1, role_idx, is_role, b1);
    gemm2_kernel<<<(MAXIT / 128) * 2, 256, DYN_SMEM>>>(a0, a1, is_role, b2);
    dim3 g(S / 32, B);
    norm_pool_kernel<<<g, 256>>>(pos_emb, ln_g, ln_b);
    final_kernel<<<1, 256>>>(lw1, lb1, lw2, lb2, out);
}

// round 16
// speedup vs baseline: 1.5950x; 1.2370x over previous
#include <cuda_runtime.h>
#include <cuda_fp16.h>
#include <math.h>
#include <stdint.h>

#define D    256
#define DL   256
#define S    2048
#define B    8
#define F    8192
#define NE   (B * F)
#define MAXIT (2 * NE)
#define TAB_PRED 2048
#define TAB_ROLE 3072
#define TAB_ROWS 3138
#define MAT_BYTES 8192
#define STAGE_BYTES (2 * MAT_BYTES)
#define NSTAGE 5
#define DYN_SMEM (NSTAGE * STAGE_BYTES + 1024)
#define SWZ(o) ((o) ^ (((o) >> 3) & 0x70))

__device__ float g_agg[B * S * D];
__device__ float g_pooled[B * D];
__device__ int   g_items[MAXIT];
__device__ int   g_count;
__device__ __align__(16) __half g_tab[TAB_ROWS * 256];
__device__ __align__(16) __half g_w1t[512 * 768];
__device__ __align__(16) __half g_w2t[256 * 512];
__device__ __align__(16) __half g_H[(size_t)MAXIT * 512];
__device__ __align__(16) float g_Pa[2048 * 512];
__device__ __align__(16) float g_Pc[2048 * 512];
__device__ __align__(16) float g_PEb[1024 * 512];
__device__ __align__(16) float g_Rc[128 * 512];

__device__ __forceinline__ uint32_t smem_u32_of(const void* p) {
    uint32_t a;
    asm("{ .reg .u64 t; cvta.to.shared.u64 t, %1; cvt.u32.u64 %0, t; }" : "=r"(a) : "l"(p));
    return a;
}
__device__ __forceinline__ float gelu_e(float x) { return x * normcdff(x); }
__device__ __forceinline__ float gelu_f(float x) {
    float x2 = x * x;
    if (fabsf(x) < 0.5f) {
        return fmaf(x2, fmaf(x2, fmaf(x2, 0.00997356f, -0.06649038f), 0.39894228f), 0.5f * x);
    }
    return x * normcdff(x);
}

#define LDSM4(r0, r1, r2, r3, addr) \
    asm volatile("ldmatrix.sync.aligned.m8n8.x4.shared.b16 {%0,%1,%2,%3}, [%4];" \
        : "=r"(r0), "=r"(r1), "=r"(r2), "=r"(r3) : "r"(addr))

#define MMA16816(c, a, b0, b1) \
    asm volatile("mma.sync.aligned.m16n8k16.row.col.f32.f16.f16.f32 " \
        "{%0,%1,%2,%3}, {%4,%5,%6,%7}, {%8,%9}, {%0,%1,%2,%3};" \
        : "+f"((c)[0]), "+f"((c)[1]), "+f"((c)[2]), "+f"((c)[3]) \
        : "r"((a)[0]), "r"((a)[1]), "r"((a)[2]), "r"((a)[3]), "r"(b0), "r"(b1))

#define CP16(dst, src) \
    asm volatile("cp.async.cg.shared.global [%0], [%1], 16;" \
        :: "r"(dst), "l"(__cvta_generic_to_global(src)) : "memory")
#define CP_COMMIT() asm volatile("cp.async.commit_group;" ::: "memory")
#define CP_WAIT3()  asm volatile("cp.async.wait_group 3;" ::: "memory")

__global__ void zero_kernel() {
    int i = blockIdx.x * blockDim.x + threadIdx.x;
    if (i < B * S * D) g_agg[i] = 0.0f;
    if (i < B * D)     g_pooled[i] = 0.0f;
    if (i == 0)        g_count = 0;
}

__global__ void compact_kernel(const int* __restrict__ mask, const int* __restrict__ is_role,
                               const int* __restrict__ add_rev) {
    int e = blockIdx.x * blockDim.x + threadIdx.x;
    if (e >= NE) return;
    if (!mask[e]) return;
    bool rev = (!is_role[e]) && add_rev[e];
    int slot = atomicAdd(&g_count, rev ? 2 : 1);
    g_items[slot] = e << 1;
    if (rev) g_items[slot + 1] = (e << 1) | 1;
}

__global__ void prep_kernel(const float* __restrict__ pos, const float* __restrict__ pred,
                            const float* __restrict__ role,
                            const float* __restrict__ w1, const float* __restrict__ w2) {
    int tid = blockIdx.x * blockDim.x + threadIdx.x;
    const int NTAB = TAB_ROWS * 256;
    const int NW1 = 512 * 768;
    const int NW2 = 256 * 512;
    if (tid < NTAB) {
        int row = tid >> 8, col = tid & 255;
        float v;
        if (row < TAB_PRED)      v = pos[tid];
        else if (row < TAB_ROLE) v = pred[(row - TAB_PRED) * 256 + col];
        else                     v = role[(row - TAB_ROLE) * 256 + col];
        g_tab[tid] = __float2half(v);
    } else if (tid < NTAB + NW1) {
        int u = tid - NTAB;
        int n = u / 768, k = u - n * 768;
        g_w1t[u] = __float2half(w1[(size_t)k * 512 + n]);
    } else if (tid < NTAB + NW1 + NW2) {
        int u = tid - NTAB - NW1;
        int n = u / 512, k = u - n * 512;
        g_w2t[u] = __float2half(w2[(size_t)k * 256 + n]);
    }
}

// ---------------- prep GEMM: table[rows] x W1-segment -> fp32 table ----------------
// X side reads table cols 0..255 (NO koff); W side uses koff (K-offset into W1).
__global__ void __launch_bounds__(256, 2)
prep_gemm_kernel(int job, int rowbase, int nrows, int koff, const float* __restrict__ bias) {
    extern __shared__ char smraw[];
    float* out = (job == 0) ? g_Pa : (job == 1) ? g_Pc : (job == 2) ? g_PEb : g_Rc;

    int t = threadIdx.x;
    int tile = blockIdx.x >> 2, nq = blockIdx.x & 3;
    int mbase = tile * 128;

    uint32_t raw = smem_u32_of(smraw);
    uint32_t smu = (raw + 1023u) & ~1023u;

    int w = t >> 5, lane = t & 31;
    int wm = w >> 1, wn = w & 1;
    int blk = lane >> 3, brow = lane & 7;

    float acc[64];
    #pragma unroll
    for (int i = 0; i < 64; i++) acc[i] = 0.0f;

    const int KC = 8;  // 256 / 32

    #define PG_FILL(kc_, st_) do { \
        uint32_t sb = smu + (st_) * STAGE_BYTES; \
        _Pragma("unroll") \
        for (int i = t; i < 512; i += 256) { \
            int e_ = i >> 2, q_ = i & 3; \
            int row_ = rowbase + mbase + e_; \
            if (row_ >= TAB_ROWS) row_ = TAB_ROWS - 1; \
            const char* src_ = (const char*)g_tab \
                               + (size_t)row_ * 512 + (kc_) * 64 + q_ * 16; \
            CP16(sb + SWZ(e_ * 64 + q_ * 16), src_); \
        } \
        _Pragma("unroll") \
        for (int i = t; i < 512; i += 256) { \
            int r_ = i >> 2, q_ = i & 3; \
            const char* src_ = (const char*)g_w1t \
                               + (size_t)(nq * 128 + r_) * 1536 + koff * 2 + (kc_) * 64 + q_ * 16; \
            CP16(sb + MAT_BYTES + SWZ(r_ * 64 + q_ * 16), src_); \
        } \
    } while (0)

    PG_FILL(0, 0); CP_COMMIT();
    PG_FILL(1, 1); CP_COMMIT();
    PG_FILL(2, 2); CP_COMMIT();
    PG_FILL(3, 3); CP_COMMIT();

    int st = 0, stn = 4;
    for (int kc = 0; kc < KC; kc++) {
        CP_WAIT3();
        __syncthreads();
        if (kc + 4 < KC) PG_FILL(kc + 4, stn);
        CP_COMMIT();

        uint32_t sb = smu + st * STAGE_BYTES;
        uint32_t x_u = sb;
        uint32_t w_u = sb + MAT_BYTES;

        #pragma unroll
        for (int kk = 0; kk < 2; kk++) {
            uint32_t ah[2][4];
            #pragma unroll
            for (int mf = 0; mf < 2; mf++) {
                uint32_t off = SWZ((uint32_t)(wm * 32 + mf * 16 + (blk & 1) * 8 + brow) * 64
                                   + kk * 32 + (blk >> 1) * 16);
                LDSM4(ah[mf][0], ah[mf][1], ah[mf][2], ah[mf][3], x_u + off);
            }
            #pragma unroll
            for (int nf2 = 0; nf2 < 4; nf2++) {
                uint32_t boff = SWZ((uint32_t)(wn * 64 + nf2 * 16 + (blk >> 1) * 8 + brow) * 64
                                    + kk * 32 + (blk & 1) * 16);
                uint32_t bh[4];
                LDSM4(bh[0], bh[1], bh[2], bh[3], w_u + boff);
                float* c0 = &acc[(nf2 * 2) * 4];
                float* c1 = &acc[(nf2 * 2 + 1) * 4];
                float* c2 = &acc[(8 + nf2 * 2) * 4];
                float* c3 = &acc[(8 + nf2 * 2 + 1) * 4];
                MMA16816(c0, ah[0], bh[0], bh[1]);
                MMA16816(c1, ah[0], bh[2], bh[3]);
                MMA16816(c2, ah[1], bh[0], bh[1]);
                MMA16816(c3, ah[1], bh[2], bh[3]);
            }
        }
        st = (st + 1 == NSTAGE) ? 0 : st + 1;
        stn = (stn + 1 == NSTAGE) ? 0 : stn + 1;
    }

    {
        int g = lane >> 2, i2 = (lane & 3) * 2;
        #pragma unroll
        for (int mh = 0; mh < 2; mh++) {
            #pragma unroll
            for (int nf2 = 0; nf2 < 4; nf2++) {
                #pragma unroll
                for (int p = 0; p < 2; p++) {
                    float* c = &acc[(mh * 8 + nf2 * 2 + p) * 4];
                    int gcol = nq * 128 + wn * 64 + nf2 * 16 + p * 8 + i2;
                    float bx = 0.f, by = 0.f;
                    if (bias) { bx = bias[gcol]; by = bias[gcol + 1]; }
                    int r0 = mbase + wm * 32 + mh * 16 + g;
                    if (r0 < nrows) {
                        float2 v = make_float2(c[0] + bx, c[1] + by);
                        *(float2*)&out[(size_t)r0 * 512 + gcol] = v;
                    }
                    if (r0 + 8 < nrows) {
                        float2 v = make_float2(c[2] + bx, c[3] + by);
                        *(float2*)&out[(size_t)(r0 + 8) * 512 + gcol] = v;
                    }
                }
            }
        }
    }
}

// ---------------- gather: H[item] = gelu(Pa[r0] + PEb[pi] + (role?Rc:Pc)) ----------------
__global__ void __launch_bounds__(256) gather_kernel(
    const int* __restrict__ pred_idx,
    const int* __restrict__ a0, const int* __restrict__ a1,
    const int* __restrict__ role_idx, const int* __restrict__ is_role) {
    int count = g_count;
    int item = blockIdx.x * 8 + (threadIdx.x >> 5);
    if (item >= count) return;
    int lane = threadIdx.x & 31;

    int it = g_items[item];
    int e = it >> 1, dir = it & 1;
    int i0 = a0[e], i1 = a1[e];
    const float* pB = g_PEb + (size_t)pred_idx[e] * 512;
    const float* pA;
    const float* pC;
    if (dir == 0) {
        int rr = is_role[e];
        pA = g_Pa + (size_t)i0 * 512;
        pC = rr ? (g_Rc + (size_t)(role_idx[e]) * 512) : (g_Pc + (size_t)i1 * 512);
    } else {
        pA = g_Pa + (size_t)i1 * 512;
        pC = g_Pc + (size_t)i0 * 512;
    }
    __half* ho = g_H + (size_t)item * 512;
    #pragma unroll
    for (int j = 0; j < 4; j++) {
        int c = lane * 4 + j * 128;
        float4 va = *(const float4*)(pA + c);
        float4 vb = *(const float4*)(pB + c);
        float4 vc = *(const float4*)(pC + c);
        float g0 = gelu_f(va.x + vb.x + vc.x);
        float g1 = gelu_f(va.y + vb.y + vc.y);
        float g2 = gelu_f(va.z + vb.z + vc.z);
        float g3 = gelu_f(va.w + vb.w + vc.w);
        *(__half2*)(ho + c) = __floats2half2_rn(g0, g1);
        *(__half2*)(ho + c + 2) = __floats2half2_rn(g2, g3);
    }
}

// ---------------- GEMM2: H[128x512] @ W2[512x256] -> +b2 -> atomic scatter ----------------
__global__ void __launch_bounds__(256, 2)
gemm2_kernel(const int* __restrict__ a0, const int* __restrict__ a1,
             const int* __restrict__ is_role, const float* __restrict__ b2) {
    extern __shared__ char smraw[];
    __shared__ int stgt[128];
    __shared__ float sb2[128];

    int t = threadIdx.x;
    int tile = blockIdx.x >> 1, nq = blockIdx.x & 1;
    int count = g_count;
    int base = tile * 128;
    if (base >= count) return;
    int nE = min(128, count - base);

    if (t < 128) {
        int tg = 0, bidx = 0;
        if (t < nE) {
            int item = g_items[base + t];
            int e = item >> 1, dir = item & 1;
            bidx = e >> 13;
            int i0 = a0[e], i1 = a1[e];
            if (dir == 0) { int rr = is_role[e]; tg = rr ? i0 : i1; }
            else tg = i0;
        }
        stgt[t] = (bidx * S + tg) * D;
        sb2[t] = b2[nq * 128 + t];
    }

    uint32_t raw = smem_u32_of(smraw);
    uint32_t smu = (raw + 1023u) & ~1023u;
    __syncthreads();

    int w = t >> 5, lane = t & 31;
    int wm = w >> 1, wn = w & 1;
    int blk = lane >> 3, brow = lane & 7;

    float acc[64];
    #pragma unroll
    for (int i = 0; i < 64; i++) acc[i] = 0.0f;

    const int KC = 16;

    #define G2_FILL(kc_, st_) do { \
        uint32_t sb = smu + (st_) * STAGE_BYTES; \
        _Pragma("unroll") \
        for (int i = t; i < 512; i += 256) { \
            int e_ = i >> 2, q_ = i & 3; \
            const char* src_ = (const char*)g_H \
                               + (size_t)(base + e_) * 1024 + (kc_) * 64 + q_ * 16; \
            CP16(sb + SWZ(e_ * 64 + q_ * 16), src_); \
        } \
        _Pragma("unroll") \
        for (int i = t; i < 512; i += 256) { \
            int r_ = i >> 2, q_ = i & 3; \
            const char* src_ = (const char*)g_w2t \
                               + (size_t)(nq * 128 + r_) * 1024 + (kc_) * 64 + q_ * 16; \
            CP16(sb + MAT_BYTES + SWZ(r_ * 64 + q_ * 16), src_); \
        } \
    } while (0)

    G2_FILL(0, 0); CP_COMMIT();
    G2_FILL(1, 1); CP_COMMIT();
    G2_FILL(2, 2); CP_COMMIT();
    G2_FILL(3, 3); CP_COMMIT();

    int st = 0, stn = 4;
    for (int kc = 0; kc < KC; kc++) {
        CP_WAIT3();
        __syncthreads();
        if (kc + 4 < KC) G2_FILL(kc + 4, stn);
        CP_COMMIT();

        uint32_t sb = smu + st * STAGE_BYTES;
        uint32_t x_u = sb;
        uint32_t w_u = sb + MAT_BYTES;

        #pragma unroll
        for (int kk = 0; kk < 2; kk++) {
            uint32_t ah[2][4];
            #pragma unroll
            for (int mf = 0; mf < 2; mf++) {
                uint32_t off = SWZ((uint32_t)(wm * 32 + mf * 16 + (blk & 1) * 8 + brow) * 64
                                   + kk * 32 + (blk >> 1) * 16);
                LDSM4(ah[mf][0], ah[mf][1], ah[mf][2], ah[mf][3], x_u + off);
            }
            #pragma unroll
            for (int nf2 = 0; nf2 < 4; nf2++) {
                uint32_t boff = SWZ((uint32_t)(wn * 64 + nf2 * 16 + (blk >> 1) * 8 + brow) * 64
                                    + kk * 32 + (blk & 1) * 16);
                uint32_t bh[4];
                LDSM4(bh[0], bh[1], bh[2], bh[3], w_u + boff);
                float* c0 = &acc[(nf2 * 2) * 4];
                float* c1 = &acc[(nf2 * 2 + 1) * 4];
                float* c2 = &acc[(8 + nf2 * 2) * 4];
                float* c3 = &acc[(8 + nf2 * 2 + 1) * 4];
                MMA16816(c0, ah[0], bh[0], bh[1]);
                MMA16816(c1, ah[0], bh[2], bh[3]);
                MMA16816(c2, ah[1], bh[0], bh[1]);
                MMA16816(c3, ah[1], bh[2], bh[3]);
            }
        }
        st = (st + 1 == NSTAGE) ? 0 : st + 1;
        stn = (stn + 1 == NSTAGE) ? 0 : stn + 1;
    }

    {
        int g = lane >> 2, i2 = (lane & 3) * 2;
        #pragma unroll
        for (int mh = 0; mh < 2; mh++) {
            #pragma unroll
            for (int nf2 = 0; nf2 < 4; nf2++) {
                #pragma unroll
                for (int p = 0; p < 2; p++) {
                    float* c = &acc[(mh * 8 + nf2 * 2 + p) * 4];
                    int lcol = wn * 64 + nf2 * 16 + p * 8 + i2;
                    int gcol = nq * 128 + lcol;
                    float2 bb = *(const float2*)&sb2[lcol];
                    int r0 = wm * 32 + mh * 16 + g;
                    if (r0 < nE) {
                        float* dst = &g_agg[stgt[r0] + gcol];
                        atomicAdd(dst,     c[0] + bb.x);
                        atomicAdd(dst + 1, c[1] + bb.y);
                    }
                    if (r0 + 8 < nE) {
                        float* dst = &g_agg[stgt[r0 + 8] + gcol];
                        atomicAdd(dst,     c[2] + bb.x);
                        atomicAdd(dst + 1, c[3] + bb.y);
                    }
                }
            }
        }
    }
}

// ---------------- layernorm + pooled mean ----------------
__global__ void norm_pool_kernel(const float* __restrict__ pos,
                                 const float* __restrict__ ln_g,
                                 const float* __restrict__ ln_b) {
    int b = blockIdx.y;
    int s_base = blockIdx.x * 32;
    int warp = threadIdx.x >> 5, lane = threadIdx.x & 31;
    float gg[8], be[8], pacc[8];
    #pragma unroll
    for (int i = 0; i < 8; i++) {
        gg[i] = ln_g[i * 32 + lane]; be[i] = ln_b[i * 32 + lane]; pacc[i] = 0.0f;
    }
    for (int r = warp; r < 32; r += 8) {
        int ss = s_base + r;
        const float* ag = &g_agg[((size_t)b * S + ss) * D];
        const float* ps = &pos[(size_t)ss * D];
        float x[8]; float sum = 0.0f;
        #pragma unroll
        for (int i = 0; i < 8; i++) { x[i] = ps[i * 32 + lane] + ag[i * 32 + lane]; sum += x[i]; }
        #pragma unroll
        for (int off = 16; off > 0; off >>= 1) sum += __shfl_xor_sync(0xFFFFFFFFu, sum, off);
        float mu = sum * (1.0f / D); float v = 0.0f;
        #pragma unroll
        for (int i = 0; i < 8; i++) { x[i] -= mu; v += x[i] * x[i]; }
        #pragma unroll
        for (int off = 16; off > 0; off >>= 1) v += __shfl_xor_sync(0xFFFFFFFFu, v, off);
        float inv = rsqrtf(v * (1.0f / D) + 1e-5f);
        #pragma unroll
        for (int i = 0; i < 8; i++) pacc[i] += x[i] * inv * gg[i] + be[i];
    }
    __shared__ float sp[256];
    sp[threadIdx.x] = 0.0f;
    __syncthreads();
    #pragma unroll
    for (int i = 0; i < 8; i++) atomicAdd(&sp[i * 32 + lane], pacc[i]);
    __syncthreads();
    atomicAdd(&g_pooled[b * D + threadIdx.x], sp[threadIdx.x] * (1.0f / S));
}

// ---------------- final small MLP ----------------
__global__ void final_kernel(const float* __restrict__ lw1, const float* __restrict__ lb1,
                             const float* __restrict__ lw2, const float* __restrict__ lb2,
                             float* __restrict__ out) {
    __shared__ float P[B * D];
    __shared__ float Hh[B * DL];
    int t = threadIdx.x;
    for (int i = t; i < B * D; i += 256) P[i] = g_pooled[i];
    __syncthreads();
    float a[B];
    #pragma unroll
    for (int b = 0; b < B; b++) a[b] = lb1[t];
    for (int k = 0; k < D; k++) {
        float wv = lw1[k * DL + t];
        #pragma unroll
        for (int b = 0; b < B; b++) a[b] = fmaf(P[b * D + k], wv, a[b]);
    }
    #pragma unroll
    for (int b = 0; b < B; b++) Hh[b * DL + t] = gelu_e(a[b]);
    __syncthreads();
    #pragma unroll
    for (int b = 0; b < B; b++) a[b] = lb2[t];
    for (int k = 0; k < DL; k++) {
        float wv = lw2[k * DL + t];
        #pragma unroll
        for (int b = 0; b < B; b++) a[b] = fmaf(Hh[b * DL + k], wv, a[b]);
    }
    #pragma unroll
    for (int b = 0; b < B; b++) out[b * DL + t] = a[b];
}

// ---------------- launch ----------------
extern "C" void kernel_launch(void* const* d_in, const int* in_sizes, int n_in,
                              void* d_out, int out_size) {
    const float* pos_emb  = (const float*)d_in[0];
    const float* pred_emb = (const float*)d_in[1];
    const float* role_emb = (const float*)d_in[2];
    const float* w1       = (const float*)d_in[3];
    const float* b1       = (const float*)d_in[4];
    const float* w2       = (const float*)d_in[5];
    const float* b2       = (const float*)d_in[6];
    const float* ln_g     = (const float*)d_in[7];
    const float* ln_b     = (const float*)d_in[8];
    const float* lw1      = (const float*)d_in[9];
    const float* lb1      = (const float*)d_in[10];
    const float* lw2      = (const float*)d_in[11];
    const float* lb2      = (const float*)d_in[12];
    const int* pred_idx   = (const int*)d_in[13];
    const int* a0         = (const int*)d_in[14];
    const int* a1         = (const int*)d_in[15];
    const int* role_idx   = (const int*)d_in[16];
    const int* is_role    = (const int*)d_in[17];
    const int* add_rev    = (const int*)d_in[18];
    const int* mask       = (const int*)d_in[19];
    float* out = (float*)d_out;

    cudaFuncSetAttribute(prep_gemm_kernel, cudaFuncAttributeMaxDynamicSharedMemorySize, DYN_SMEM);
    cudaFuncSetAttribute(gemm2_kernel, cudaFuncAttributeMaxDynamicSharedMemorySize, DYN_SMEM);

    zero_kernel<<<(B * S * D + 255) / 256, 256>>>();
    compact_kernel<<<(NE + 255) / 256, 256>>>(mask, is_role, add_rev);
    {
        int total = TAB_ROWS * 256 + 512 * 768 + 256 * 512;
        prep_kernel<<<(total + 255) / 256, 256>>>(pos_emb, pred_emb, role_emb, w1, w2);
    }
    // layer-1 tables: Pa, Pc, PEb(+b1), Rc
    prep_gemm_kernel<<<16 * 4, 256, DYN_SMEM>>>(0, 0, 2048, 0, nullptr);
    prep_gemm_kernel<<<16 * 4, 256, DYN_SMEM>>>(1, 0, 2048, 512, nullptr);
    prep_gemm_kernel<<<8 * 4, 256, DYN_SMEM>>>(2, TAB_PRED, 1024, 256, b1);
    prep_gemm_kernel<<<1 * 4, 256, DYN_SMEM>>>(3, TAB_ROLE, 66, 512, nullptr);
    // layer-1 per-item: gather + add + gelu -> g_H
    gather_kernel<<<MAXIT / 8, 256>>>(pred_idx, a0, a1, role_idx, is_role);
    // layer-2 GEMM + scatter
    gemm2_kernel<<<(MAXIT / 128) * 2, 256, DYN_SMEM>>>(a0, a1, is_role, b2);
    dim3 g(S / 32, B);
    norm_pool_kernel<<<g, 256>>>(pos_emb, ln_g, ln_b);
    final_kernel<<<1, 256>>>(lw1, lb1, lw2, lb2, out);
}

// round 17
// speedup vs baseline: 1.6987x; 1.0650x over previous
#include <cuda_runtime.h>
#include <cuda_fp16.h>
#include <math.h>
#include <stdint.h>

#define D    256
#define DL   256
#define S    2048
#define B    8
#define F    8192
#define NE   (B * F)
#define MAXIT (2 * NE)
#define TAB_PRED 2048
#define TAB_ROLE 3072
#define TAB_ROWS 3138
#define MAT_BYTES 8192
#define STAGE_BYTES (2 * MAT_BYTES)
#define NSTAGE 5
#define DYN_SMEM (NSTAGE * STAGE_BYTES + 1024)
#define SWZ(o) ((o) ^ (((o) >> 3) & 0x70))

__device__ float g_agg[B * S * D];
__device__ float g_pooled[B * D];
__device__ int   g_items[MAXIT];
__device__ int   g_count;
__device__ __align__(16) __half g_tab[TAB_ROWS * 256];
__device__ __align__(16) __half g_w1t[512 * 768];
__device__ __align__(16) __half g_w2t[256 * 512];
__device__ __align__(16) __half g_H[(size_t)MAXIT * 512];
// precomputed layer-1 tables (fp16)
__device__ __align__(16) __half g_Pa[2048 * 512];
__device__ __align__(16) __half g_Pc[2048 * 512];
__device__ __align__(16) __half g_PEb[1024 * 512];
__device__ __align__(16) __half g_Rc[128 * 512];

__device__ __forceinline__ uint32_t smem_u32_of(const void* p) {
    uint32_t a;
    asm("{ .reg .u64 t; cvta.to.shared.u64 t, %1; cvt.u32.u64 %0, t; }" : "=r"(a) : "l"(p));
    return a;
}
__device__ __forceinline__ float gelu_e(float x) { return x * normcdff(x); }
__device__ __forceinline__ float gelu_f(float x) {
    float x2 = x * x;
    if (fabsf(x) < 0.5f) {
        return fmaf(x2, fmaf(x2, fmaf(x2, 0.00997356f, -0.06649038f), 0.39894228f), 0.5f * x);
    }
    return x * normcdff(x);
}

#define LDSM4(r0, r1, r2, r3, addr) \
    asm volatile("ldmatrix.sync.aligned.m8n8.x4.shared.b16 {%0,%1,%2,%3}, [%4];" \
        : "=r"(r0), "=r"(r1), "=r"(r2), "=r"(r3) : "r"(addr))

#define MMA16816(c, a, b0, b1) \
    asm volatile("mma.sync.aligned.m16n8k16.row.col.f32.f16.f16.f32 " \
        "{%0,%1,%2,%3}, {%4,%5,%6,%7}, {%8,%9}, {%0,%1,%2,%3};" \
        : "+f"((c)[0]), "+f"((c)[1]), "+f"((c)[2]), "+f"((c)[3]) \
        : "r"((a)[0]), "r"((a)[1]), "r"((a)[2]), "r"((a)[3]), "r"(b0), "r"(b1))

#define CP16(dst, src) \
    asm volatile("cp.async.cg.shared.global [%0], [%1], 16;" \
        :: "r"(dst), "l"(__cvta_generic_to_global(src)) : "memory")
#define CP_COMMIT() asm volatile("cp.async.commit_group;" ::: "memory")
#define CP_WAIT3()  asm volatile("cp.async.wait_group 3;" ::: "memory")

__global__ void zero_kernel() {
    int i = blockIdx.x * blockDim.x + threadIdx.x;
    if (i < B * S * D) g_agg[i] = 0.0f;
    if (i < B * D)     g_pooled[i] = 0.0f;
    if (i == 0)        g_count = 0;
}

__global__ void compact_kernel(const int* __restrict__ mask, const int* __restrict__ is_role,
                               const int* __restrict__ add_rev) {
    int e = blockIdx.x * blockDim.x + threadIdx.x;
    if (e >= NE) return;
    if (!mask[e]) return;
    bool rev = (!is_role[e]) && add_rev[e];
    int slot = atomicAdd(&g_count, rev ? 2 : 1);
    g_items[slot] = e << 1;
    if (rev) g_items[slot + 1] = (e << 1) | 1;
}

__global__ void prep_kernel(const float* __restrict__ pos, const float* __restrict__ pred,
                            const float* __restrict__ role,
                            const float* __restrict__ w1, const float* __restrict__ w2) {
    int tid = blockIdx.x * blockDim.x + threadIdx.x;
    const int NTAB = TAB_ROWS * 256;
    const int NW1 = 512 * 768;
    const int NW2 = 256 * 512;
    if (tid < NTAB) {
        int row = tid >> 8, col = tid & 255;
        float v;
        if (row < TAB_PRED)      v = pos[tid];
        else if (row < TAB_ROLE) v = pred[(row - TAB_PRED) * 256 + col];
        else                     v = role[(row - TAB_ROLE) * 256 + col];
        g_tab[tid] = __float2half(v);
    } else if (tid < NTAB + NW1) {
        int u = tid - NTAB;
        int n = u / 768, k = u - n * 768;
        g_w1t[u] = __float2half(w1[(size_t)k * 512 + n]);
    } else if (tid < NTAB + NW1 + NW2) {
        int u = tid - NTAB - NW1;
        int n = u / 512, k = u - n * 512;
        g_w2t[u] = __float2half(w2[(size_t)k * 256 + n]);
    }
}

// ---------------- prep GEMM (all 4 jobs in one launch): table x W1-seg -> fp16 table ----
// bi<16: Pa(pos,koff=0) | bi<32: Pc(pos,koff=512) | bi<40: PEb(pred,koff=256,+b1) | Rc(role,koff=512)
__global__ void __launch_bounds__(256, 2)
prep_gemm_kernel(const float* __restrict__ b1) {
    extern __shared__ char smraw[];
    int bi = blockIdx.x >> 2, nq = blockIdx.x & 3;

    int tile, rowbase, nrows, koff;
    __half* out;
    const float* bias = nullptr;
    if (bi < 16)      { out = g_Pa;  tile = bi;      rowbase = 0;        nrows = 2048; koff = 0; }
    else if (bi < 32) { out = g_Pc;  tile = bi - 16; rowbase = 0;        nrows = 2048; koff = 512; }
    else if (bi < 40) { out = g_PEb; tile = bi - 32; rowbase = TAB_PRED; nrows = 1024; koff = 256; bias = b1; }
    else              { out = g_Rc;  tile = bi - 40; rowbase = TAB_ROLE; nrows = 66;   koff = 512; }

    int t = threadIdx.x;
    int mbase = tile * 128;

    uint32_t raw = smem_u32_of(smraw);
    uint32_t smu = (raw + 1023u) & ~1023u;

    int w = t >> 5, lane = t & 31;
    int wm = w >> 1, wn = w & 1;
    int blk = lane >> 3, brow = lane & 7;

    float acc[64];
    #pragma unroll
    for (int i = 0; i < 64; i++) acc[i] = 0.0f;

    const int KC = 8;  // 256 / 32

    #define PG_FILL(kc_, st_) do { \
        uint32_t sb = smu + (st_) * STAGE_BYTES; \
        _Pragma("unroll") \
        for (int i = t; i < 512; i += 256) { \
            int e_ = i >> 2, q_ = i & 3; \
            int row_ = rowbase + mbase + e_; \
            if (row_ >= TAB_ROWS) row_ = TAB_ROWS - 1; \
            const char* src_ = (const char*)g_tab \
                               + (size_t)row_ * 512 + (kc_) * 64 + q_ * 16; \
            CP16(sb + SWZ(e_ * 64 + q_ * 16), src_); \
        } \
        _Pragma("unroll") \
        for (int i = t; i < 512; i += 256) { \
            int r_ = i >> 2, q_ = i & 3; \
            const char* src_ = (const char*)g_w1t \
                               + (size_t)(nq * 128 + r_) * 1536 + koff * 2 + (kc_) * 64 + q_ * 16; \
            CP16(sb + MAT_BYTES + SWZ(r_ * 64 + q_ * 16), src_); \
        } \
    } while (0)

    PG_FILL(0, 0); CP_COMMIT();
    PG_FILL(1, 1); CP_COMMIT();
    PG_FILL(2, 2); CP_COMMIT();
    PG_FILL(3, 3); CP_COMMIT();

    int st = 0, stn = 4;
    for (int kc = 0; kc < KC; kc++) {
        CP_WAIT3();
        __syncthreads();
        if (kc + 4 < KC) PG_FILL(kc + 4, stn);
        CP_COMMIT();

        uint32_t sb = smu + st * STAGE_BYTES;
        uint32_t x_u = sb;
        uint32_t w_u = sb + MAT_BYTES;

        #pragma unroll
        for (int kk = 0; kk < 2; kk++) {
            uint32_t ah[2][4];
            #pragma unroll
            for (int mf = 0; mf < 2; mf++) {
                uint32_t off = SWZ((uint32_t)(wm * 32 + mf * 16 + (blk & 1) * 8 + brow) * 64
                                   + kk * 32 + (blk >> 1) * 16);
                LDSM4(ah[mf][0], ah[mf][1], ah[mf][2], ah[mf][3], x_u + off);
            }
            #pragma unroll
            for (int nf2 = 0; nf2 < 4; nf2++) {
                uint32_t boff = SWZ((uint32_t)(wn * 64 + nf2 * 16 + (blk >> 1) * 8 + brow) * 64
                                    + kk * 32 + (blk & 1) * 16);
                uint32_t bh[4];
                LDSM4(bh[0], bh[1], bh[2], bh[3], w_u + boff);
                float* c0 = &acc[(nf2 * 2) * 4];
                float* c1 = &acc[(nf2 * 2 + 1) * 4];
                float* c2 = &acc[(8 + nf2 * 2) * 4];
                float* c3 = &acc[(8 + nf2 * 2 + 1) * 4];
                MMA16816(c0, ah[0], bh[0], bh[1]);
                MMA16816(c1, ah[0], bh[2], bh[3]);
                MMA16816(c2, ah[1], bh[0], bh[1]);
                MMA16816(c3, ah[1], bh[2], bh[3]);
            }
        }
        st = (st + 1 == NSTAGE) ? 0 : st + 1;
        stn = (stn + 1 == NSTAGE) ? 0 : stn + 1;
    }

    // fragment-direct fp16 store (+ optional bias)
    {
        int g = lane >> 2, i2 = (lane & 3) * 2;
        #pragma unroll
        for (int mh = 0; mh < 2; mh++) {
            #pragma unroll
            for (int nf2 = 0; nf2 < 4; nf2++) {
                #pragma unroll
                for (int p = 0; p < 2; p++) {
                    float* c = &acc[(mh * 8 + nf2 * 2 + p) * 4];
                    int gcol = nq * 128 + wn * 64 + nf2 * 16 + p * 8 + i2;
                    float bx = 0.f, by = 0.f;
                    if (bias) { bx = bias[gcol]; by = bias[gcol + 1]; }
                    int r0 = mbase + wm * 32 + mh * 16 + g;
                    if (r0 < nrows)
                        *(__half2*)&out[(size_t)r0 * 512 + gcol] =
                            __floats2half2_rn(c[0] + bx, c[1] + by);
                    if (r0 + 8 < nrows)
                        *(__half2*)&out[(size_t)(r0 + 8) * 512 + gcol] =
                            __floats2half2_rn(c[2] + bx, c[3] + by);
                }
            }
        }
    }
}

// ---------------- gather: H[item] = gelu(Pa[r0] + PEb[pi] + (role?Rc:Pc)) ----------------
// fp16 tables; one warp per item; 6 LDG.128 + 1 STG.128 per lane
__global__ void __launch_bounds__(256) gather_kernel(
    const int* __restrict__ pred_idx,
    const int* __restrict__ a0, const int* __restrict__ a1,
    const int* __restrict__ role_idx, const int* __restrict__ is_role) {
    int count = g_count;
    int item = blockIdx.x * 8 + (threadIdx.x >> 5);
    if (item >= count) return;
    int lane = threadIdx.x & 31;

    int it = g_items[item];
    int e = it >> 1, dir = it & 1;
    int i0 = a0[e], i1 = a1[e];
    const __half* pB = g_PEb + (size_t)pred_idx[e] * 512;
    const __half* pA;
    const __half* pC;
    if (dir == 0) {
        int rr = is_role[e];
        pA = g_Pa + (size_t)i0 * 512;
        pC = rr ? (g_Rc + (size_t)role_idx[e] * 512) : (g_Pc + (size_t)i1 * 512);
    } else {
        pA = g_Pa + (size_t)i1 * 512;
        pC = g_Pc + (size_t)i0 * 512;
    }
    __half* ho = g_H + (size_t)item * 512;
    #pragma unroll
    for (int j = 0; j < 2; j++) {
        int c = lane * 8 + j * 256;
        uint4 va = *(const uint4*)(pA + c);
        uint4 vb = *(const uint4*)(pB + c);
        uint4 vc = *(const uint4*)(pC + c);
        uint4 vo;
        #pragma unroll
        for (int m = 0; m < 4; m++) {
            float2 fa = __half22float2(((const __half2*)&va)[m]);
            float2 fb = __half22float2(((const __half2*)&vb)[m]);
            float2 fc = __half22float2(((const __half2*)&vc)[m]);
            __half2 h = __floats2half2_rn(gelu_f(fa.x + fb.x + fc.x),
                                          gelu_f(fa.y + fb.y + fc.y));
            ((__half2*)&vo)[m] = h;
        }
        *(uint4*)(ho + c) = vo;
    }
}

// ---------------- GEMM2: H[128x512] @ W2[512x256] -> +b2 -> atomic scatter ----------------
__global__ void __launch_bounds__(256, 2)
gemm2_kernel(const int* __restrict__ a0, const int* __restrict__ a1,
             const int* __restrict__ is_role, const float* __restrict__ b2) {
    extern __shared__ char smraw[];
    __shared__ int stgt[128];
    __shared__ float sb2[128];

    int t = threadIdx.x;
    int tile = blockIdx.x >> 1, nq = blockIdx.x & 1;
    int count = g_count;
    int base = tile * 128;
    if (base >= count) return;
    int nE = min(128, count - base);

    if (t < 128) {
        int tg = 0, bidx = 0;
        if (t < nE) {
            int item = g_items[base + t];
            int e = item >> 1, dir = item & 1;
            bidx = e >> 13;
            int i0 = a0[e], i1 = a1[e];
            if (dir == 0) { int rr = is_role[e]; tg = rr ? i0 : i1; }
            else tg = i0;
        }
        stgt[t] = (bidx * S + tg) * D;
        sb2[t] = b2[nq * 128 + t];
    }

    uint32_t raw = smem_u32_of(smraw);
    uint32_t smu = (raw + 1023u) & ~1023u;
    __syncthreads();

    int w = t >> 5, lane = t & 31;
    int wm = w >> 1, wn = w & 1;
    int blk = lane >> 3, brow = lane & 7;

    float acc[64];
    #pragma unroll
    for (int i = 0; i < 64; i++) acc[i] = 0.0f;

    const int KC = 16;

    #define G2_FILL(kc_, st_) do { \
        uint32_t sb = smu + (st_) * STAGE_BYTES; \
        _Pragma("unroll") \
        for (int i = t; i < 512; i += 256) { \
            int e_ = i >> 2, q_ = i & 3; \
            const char* src_ = (const char*)g_H \
                               + (size_t)(base + e_) * 1024 + (kc_) * 64 + q_ * 16; \
            CP16(sb + SWZ(e_ * 64 + q_ * 16), src_); \
        } \
        _Pragma("unroll") \
        for (int i = t; i < 512; i += 256) { \
            int r_ = i >> 2, q_ = i & 3; \
            const char* src_ = (const char*)g_w2t \
                               + (size_t)(nq * 128 + r_) * 1024 + (kc_) * 64 + q_ * 16; \
            CP16(sb + MAT_BYTES + SWZ(r_ * 64 + q_ * 16), src_); \
        } \
    } while (0)

    G2_FILL(0, 0); CP_COMMIT();
    G2_FILL(1, 1); CP_COMMIT();
    G2_FILL(2, 2); CP_COMMIT();
    G2_FILL(3, 3); CP_COMMIT();

    int st = 0, stn = 4;
    for (int kc = 0; kc < KC; kc++) {
        CP_WAIT3();
        __syncthreads();
        if (kc + 4 < KC) G2_FILL(kc + 4, stn);
        CP_COMMIT();

        uint32_t sb = smu + st * STAGE_BYTES;
        uint32_t x_u = sb;
        uint32_t w_u = sb + MAT_BYTES;

        #pragma unroll
        for (int kk = 0; kk < 2; kk++) {
            uint32_t ah[2][4];
            #pragma unroll
            for (int mf = 0; mf < 2; mf++) {
                uint32_t off = SWZ((uint32_t)(wm * 32 + mf * 16 + (blk & 1) * 8 + brow) * 64
                                   + kk * 32 + (blk >> 1) * 16);
                LDSM4(ah[mf][0], ah[mf][1], ah[mf][2], ah[mf][3], x_u + off);
            }
            #pragma unroll
            for (int nf2 = 0; nf2 < 4; nf2++) {
                uint32_t boff = SWZ((uint32_t)(wn * 64 + nf2 * 16 + (blk >> 1) * 8 + brow) * 64
                                    + kk * 32 + (blk & 1) * 16);
                uint32_t bh[4];
                LDSM4(bh[0], bh[1], bh[2], bh[3], w_u + boff);
                float* c0 = &acc[(nf2 * 2) * 4];
                float* c1 = &acc[(nf2 * 2 + 1) * 4];
                float* c2 = &acc[(8 + nf2 * 2) * 4];
                float* c3 = &acc[(8 + nf2 * 2 + 1) * 4];
                MMA16816(c0, ah[0], bh[0], bh[1]);
                MMA16816(c1, ah[0], bh[2], bh[3]);
                MMA16816(c2, ah[1], bh[0], bh[1]);
                MMA16816(c3, ah[1], bh[2], bh[3]);
            }
        }
        st = (st + 1 == NSTAGE) ? 0 : st + 1;
        stn = (stn + 1 == NSTAGE) ? 0 : stn + 1;
    }

    {
        int g = lane >> 2, i2 = (lane & 3) * 2;
        #pragma unroll
        for (int mh = 0; mh < 2; mh++) {
            #pragma unroll
            for (int nf2 = 0; nf2 < 4; nf2++) {
                #pragma unroll
                for (int p = 0; p < 2; p++) {
                    float* c = &acc[(mh * 8 + nf2 * 2 + p) * 4];
                    int lcol = wn * 64 + nf2 * 16 + p * 8 + i2;
                    int gcol = nq * 128 + lcol;
                    float2 bb = *(const float2*)&sb2[lcol];
                    int r0 = wm * 32 + mh * 16 + g;
                    if (r0 < nE) {
                        float* dst = &g_agg[stgt[r0] + gcol];
                        atomicAdd(dst,     c[0] + bb.x);
                        atomicAdd(dst + 1, c[1] + bb.y);
                    }
                    if (r0 + 8 < nE) {
                        float* dst = &g_agg[stgt[r0 + 8] + gcol];
                        atomicAdd(dst,     c[2] + bb.x);
                        atomicAdd(dst + 1, c[3] + bb.y);
                    }
                }
            }
        }
    }
}

// ---------------- layernorm + pooled mean ----------------
__global__ void norm_pool_kernel(const float* __restrict__ pos,
                                 const float* __restrict__ ln_g,
                                 const float* __restrict__ ln_b) {
    int b = blockIdx.y;
    int s_base = blockIdx.x * 32;
    int warp = threadIdx.x >> 5, lane = threadIdx.x & 31;
    float gg[8], be[8], pacc[8];
    #pragma unroll
    for (int i = 0; i < 8; i++) {
        gg[i] = ln_g[i * 32 + lane]; be[i] = ln_b[i * 32 + lane]; pacc[i] = 0.0f;
    }
    for (int r = warp; r < 32; r += 8) {
        int ss = s_base + r;
        const float* ag = &g_agg[((size_t)b * S + ss) * D];
        const float* ps = &pos[(size_t)ss * D];
        float x[8]; float sum = 0.0f;
        #pragma unroll
        for (int i = 0; i < 8; i++) { x[i] = ps[i * 32 + lane] + ag[i * 32 + lane]; sum += x[i]; }
        #pragma unroll
        for (int off = 16; off > 0; off >>= 1) sum += __shfl_xor_sync(0xFFFFFFFFu, sum, off);
        float mu = sum * (1.0f / D); float v = 0.0f;
        #pragma unroll
        for (int i = 0; i < 8; i++) { x[i] -= mu; v += x[i] * x[i]; }
        #pragma unroll
        for (int off = 16; off > 0; off >>= 1) v += __shfl_xor_sync(0xFFFFFFFFu, v, off);
        float inv = rsqrtf(v * (1.0f / D) + 1e-5f);
        #pragma unroll
        for (int i = 0; i < 8; i++) pacc[i] += x[i] * inv * gg[i] + be[i];
    }
    __shared__ float sp[256];
    sp[threadIdx.x] = 0.0f;
    __syncthreads();
    #pragma unroll
    for (int i = 0; i < 8; i++) atomicAdd(&sp[i * 32 + lane], pacc[i]);
    __syncthreads();
    atomicAdd(&g_pooled[b * D + threadIdx.x], sp[threadIdx.x] * (1.0f / S));
}

// ---------------- final small MLP ----------------
__global__ void final_kernel(const float* __restrict__ lw1, const float* __restrict__ lb1,
                             const float* __restrict__ lw2, const float* __restrict__ lb2,
                             float* __restrict__ out) {
    __shared__ float P[B * D];
    __shared__ float Hh[B * DL];
    int t = threadIdx.x;
    for (int i = t; i < B * D; i += 256) P[i] = g_pooled[i];
    __syncthreads();
    float a[B];
    #pragma unroll
    for (int b = 0; b < B; b++) a[b] = lb1[t];
    for (int k = 0; k < D; k++) {
        float wv = lw1[k * DL + t];
        #pragma unroll
        for (int b = 0; b < B; b++) a[b] = fmaf(P[b * D + k], wv, a[b]);
    }
    #pragma unroll
    for (int b = 0; b < B; b++) Hh[b * DL + t] = gelu_e(a[b]);
    __syncthreads();
    #pragma unroll
    for (int b = 0; b < B; b++) a[b] = lb2[t];
    for (int k = 0; k < DL; k++) {
        float wv = lw2[k * DL + t];
        #pragma unroll
        for (int b = 0; b < B; b++) a[b] = fmaf(Hh[b * DL + k], wv, a[b]);
    }
    #pragma unroll
    for (int b = 0; b < B; b++) out[b * DL + t] = a[b];
}

// ---------------- launch ----------------
extern "C" void kernel_launch(void* const* d_in, const int* in_sizes, int n_in,
                              void* d_out, int out_size) {
    const float* pos_emb  = (const float*)d_in[0];
    const float* pred_emb = (const float*)d_in[1];
    const float* role_emb = (const float*)d_in[2];
    const float* w1       = (const float*)d_in[3];
    const float* b1       = (const float*)d_in[4];
    const float* w2       = (const float*)d_in[5];
    const float* b2       = (const float*)d_in[6];
    const float* ln_g     = (const float*)d_in[7];
    const float* ln_b     = (const float*)d_in[8];
    const float* lw1      = (const float*)d_in[9];
    const float* lb1      = (const float*)d_in[10];
    const float* lw2      = (const float*)d_in[11];
    const float* lb2      = (const float*)d_in[12];
    const int* pred_idx   = (const int*)d_in[13];
    const int* a0         = (const int*)d_in[14];
    const int* a1         = (const int*)d_in[15];
    const int* role_idx   = (const int*)d_in[16];
    const int* is_role    = (const int*)d_in[17];
    const int* add_rev    = (const int*)d_in[18];
    const int* mask       = (const int*)d_in[19];
    float* out = (float*)d_out;

    cudaFuncSetAttribute(prep_gemm_kernel, cudaFuncAttributeMaxDynamicSharedMemorySize, DYN_SMEM);
    cudaFuncSetAttribute(gemm2_kernel, cudaFuncAttributeMaxDynamicSharedMemorySize, DYN_SMEM);

    zero_kernel<<<(B * S * D + 255) / 256, 256>>>();
    compact_kernel<<<(NE + 255) / 256, 256>>>(mask, is_role, add_rev);
    {
        int total = TAB_ROWS * 256 + 512 * 768 + 256 * 512;
        prep_kernel<<<(total + 255) / 256, 256>>>(pos_emb, pred_emb, role_emb, w1, w2);
    }
    // all 4 layer-1 tables in one launch (41 row-tiles x 4 n-quarters)
    prep_gemm_kernel<<<41 * 4, 256, DYN_SMEM>>>(b1);
    // layer-1 per-item: gather + add + gelu -> g_H
    gather_kernel<<<MAXIT / 8, 256>>>(pred_idx, a0, a1, role_idx, is_role);
    // layer-2 GEMM + scatter
    gemm2_kernel<<<(MAXIT / 128) * 2, 256, DYN_SMEM>>>(a0, a1, is_role, b2);
    dim3 g(S / 32, B);
    norm_pool_kernel<<<g, 256>>>(pos_emb, ln_g, ln_b);
    final_kernel<<<1, 256>>>(lw1, lb1, lw2, lb2, out);
}